// round 15
// baseline (speedup 1.0000x reference)
#include <cuda_runtime.h>
#include <cuda_fp16.h>
#include <cstdint>
#include <math.h>

#define SEQ   2048
#define HD    128
#define NROT  64
#define NROWS (4 * 2048 * 32)     // 262144 rows of 128
#define TILES64 (NROWS / 64)      // 4096 tiles of 64 rows
#define GRID  304                 // 2 CTAs per SM
#define NTHREADS 256

// SMEM layout (bytes) — ~111KB per CTA, 2 CTAs/SM
#define SMEM_B    0               // 32KB: B fragments fp16
#define SMEM_A    32768           // 2 bufs x 16KB (fp16 x-tile, 64 rows)
#define SMEM_ST   65536           // 32KB f32 epilogue stage
// M region (prologue only) aliases A+ST: smem+32768 .. +98304 (64KB)
#define SMEM_M    32768
#define SMEM_SC   98304           // up to 14 tiles * 2 pos * 64 freq * 8B = 14336
#define SMEM_PAR  112640          // cs[64], sn[64], ij[128]  (1KB)
#define SMEM_SZ   113664

// ---------------- helpers ----------------
__device__ __forceinline__ uint32_t smem_u32(const void* p) {
    uint32_t a;
    asm("{ .reg .u64 t; cvta.to.shared.u64 t, %1; cvt.u32.u64 %0, t; }" : "=r"(a) : "l"(p));
    return a;
}

#define LDMATRIX_X4(r, addr) \
    asm volatile("ldmatrix.sync.aligned.m8n8.x4.shared.b16 {%0,%1,%2,%3}, [%4];" \
        : "=r"((r)[0]), "=r"((r)[1]), "=r"((r)[2]), "=r"((r)[3]) : "r"(addr))

#define MMA16816(d, a, b0v, b1v) \
    asm volatile("mma.sync.aligned.m16n8k16.row.col.f32.f16.f16.f32 " \
        "{%0,%1,%2,%3}, {%4,%5,%6,%7}, {%8,%9}, {%0,%1,%2,%3};" \
        : "+f"((d)[0]), "+f"((d)[1]), "+f"((d)[2]), "+f"((d)[3]) \
        : "r"((a)[0]), "r"((a)[1]), "r"((a)[2]), "r"((a)[3]), "r"(b0v), "r"(b1v))

// A tile SMEM layout (fp16, 16KB, 64 rows): row-major 256B/row, 16B chunks
// XOR-swizzled per 8-row group.
__device__ __forceinline__ void convert_one(float4 v, int g, uint32_t abase) {
    int r = g >> 5;
    int c = g & 31;
    __half2 p01 = __floats2half2_rn(v.x, v.y);
    __half2 p23 = __floats2half2_rn(v.z, v.w);
    uint32_t h01 = *(uint32_t*)&p01;
    uint32_t h23 = *(uint32_t*)&p23;
    uint32_t off = ((uint32_t)r << 8) + (((((uint32_t)c >> 1) ^ (r & 7)) & 15) << 4)
                 + ((c & 1) << 3);
    asm volatile("st.shared.v2.b32 [%0], {%1, %2};" :: "r"(abase + off), "r"(h01), "r"(h23));
}

// ---------------- single fused kernel ----------------
__global__ void __launch_bounds__(NTHREADS, 2)
rotary_mma(const float* __restrict__ x, float* __restrict__ out,
           const float* __restrict__ thetas, const float* __restrict__ pairs,
           const float* __restrict__ scale,  const float* __restrict__ Rm,
           const float* __restrict__ inv_freq) {
    extern __shared__ char smem[];
    const uint32_t sb = smem_u32(smem);
    const int tid  = threadIdx.x;
    const int bid  = blockIdx.x;
    const int warp = tid >> 5;
    const int lane = tid & 31;
    const int wm   = warp >> 2;          // 0..1 : 32-row strip (= seq-pos slot)
    const int wn   = warp & 3;           // 0..3 : 32-col strip
    const int gq   = lane >> 2;          // 0..7
    const int tq   = lane & 3;           // 0..3

    const int nt = (TILES64 - bid + GRID - 1) / GRID;   // 13 or 14

    float (*M)[HD] = (float (*)[HD])(smem + SMEM_M);
    float* cs = (float*)(smem + SMEM_PAR);
    float* sn = cs + 64;
    int*   ij = (int*)(sn + 64);
    float2* sc_s = (float2*)(smem + SMEM_SC);

    // ---- prologue phase 1: load Rm into M (aliases A+stage); stage params ----
    {
        const float4* src = (const float4*)Rm;
        float4* dst = (float4*)(smem + SMEM_M);
        #pragma unroll
        for (int i = 0; i < 16; i++) dst[tid + i * 256] = src[tid + i * 256];
    }
    if (tid >= 128 && tid < 192) {
        int k = tid - 128;
        float th = thetas[k] * scale[0];
        float s, c;
        sincosf(th, &s, &c);
        cs[k] = c; sn[k] = s;
        ij[k]      = (int)pairs[2 * k];
        ij[64 + k] = (int)pairs[2 * k + 1];
    }
    __syncthreads();

    // ---- prologue phase 2 (split): fold (t<128) || sin/cos table (t>=128) ----
    if (tid < 128) {
        // barrier-free column-owner fold: M <- E1..E64 * Rm
        const int c = tid;
        #pragma unroll 4
        for (int k = NROT - 1; k >= 0; k--) {
            int   i   = ij[k];
            int   j   = ij[64 + k];
            float cth = cs[k], sth = sn[k];
            float mi = M[i][c];
            if (i == j) {
                M[i][c] = cth * mi;
            } else {
                float mj = M[j][c];
                M[i][c] = cth * mi - sth * mj;
                M[j][c] = sth * mi + cth * mj;
            }
        }
    } else {
        // this CTA's private (pos, freq) sin/cos table
        for (int e = tid - 128; e < nt * 128; e += 128) {
            int j = e >> 7;
            int q = (e >> 6) & 1;
            int d = e & 63;
            int pos = (((bid + j * GRID) << 1) + q) & (SEQ - 1);
            float a = (float)pos * inv_freq[d];
            float sv, cv;
            sincosf(a, &sv, &cv);
            sc_s[e] = make_float2(sv, cv);
        }
    }
    __syncthreads();

    // ---- prologue phase 3: pack B fragments into SMEM_B ----
    {
        uint2* bp2 = (uint2*)(smem + SMEM_B);
        #pragma unroll
        for (int r = 0; r < 16; r++) {
            int e = tid + r * 256;            // 0..4095
            int half = e & 1;
            int ln   = (e >> 1) & 31;
            int c2   = (e >> 6) & 1;
            int wnn  = (e >> 7) & 3;
            int kt   = (e >> 9) & 7;
            int tqq  = ln & 3;
            int nr   = ln >> 2;
            int n    = (wnn * 4 + c2 * 2 + half) * 8 + nr;
            int k0   = kt * 16 + tqq * 2;
            uint32_t w[4];
            #pragma unroll
            for (int q = 0; q < 4; q++) {
                int k = k0 + (q >> 1) * 8 + (q & 1);
                __half h = __float2half_rn(M[k][n]);
                w[q] = (uint32_t)*(uint16_t*)&h;
            }
            bp2[e] = make_uint2(w[0] | (w[1] << 16), w[2] | (w[3] << 16));
        }
    }
    __syncthreads();

    const float4* x4 = (const float4*)x;
    float4*       o4 = (float4*)out;
    const uint4*  Bf = (const uint4*)(smem + SMEM_B);

    // ldmatrix per-thread address pieces
    const int lr = lane & 15;
    const int lc = lane >> 4;
    const uint32_t sw = lr & 7;
    uint32_t rowoff[2];
    rowoff[0] = (uint32_t)(wm * 32 + lr) << 8;
    rowoff[1] = (uint32_t)(wm * 32 + 16 + lr) << 8;

    // prologue: convert tile 0 into A[0] (overwrites dead M region)
    {
        const float4* xs = x4 + (size_t)bid * 2048;
        #pragma unroll
        for (int i = 0; i < 8; i++)
            convert_one(xs[tid + i * NTHREADS], tid + i * NTHREADS, sb + SMEM_A);
    }
    __syncthreads();

    for (int it = 0; it < nt; it++) {
        const int buf  = it & 1;
        const int tile = bid + it * GRID;
        const uint32_t abase = sb + SMEM_A + (uint32_t)buf * 16384;
        const uint32_t anext = sb + SMEM_A + (uint32_t)(buf ^ 1) * 16384;
        const bool have_next = (it + 1 < nt);

        // sin/cos for this warp's position + this thread's 4 freq columns (LDS)
        float2 scv[4];
        {
            const float2* scp = sc_s + (it * 2 + wm) * 64 + wn * 16 + tq;
            #pragma unroll
            for (int n = 0; n < 4; n++) scv[n] = scp[n * 4];
        }

        float acc[2][4][4];
        #pragma unroll
        for (int m = 0; m < 2; m++)
            #pragma unroll
            for (int n = 0; n < 4; n++)
                #pragma unroll
                for (int e = 0; e < 4; e++) acc[m][n][e] = 0.f;

        // pipelined next-tile fetch: 8 float4 per thread
        const float4* xs = x4 + (size_t)(tile + GRID) * 2048;
        float4 q0[8];
        if (have_next) {
            #pragma unroll
            for (int c = 0; c < 4; c++) q0[c] = xs[tid + c * NTHREADS];
        }

        #pragma unroll
        for (int kt = 0; kt < 8; kt++) {
            if (have_next && kt < 4)
                q0[kt + 4] = xs[tid + (kt + 4) * NTHREADS];
            uint32_t A2[2][4];
            const uint32_t choff = ((((uint32_t)(kt * 2 + lc)) ^ sw) & 15) << 4;
            #pragma unroll
            for (int m = 0; m < 2; m++)
                LDMATRIX_X4(A2[m], abase + rowoff[m] + choff);
            #pragma unroll
            for (int c2 = 0; c2 < 2; c2++) {
                uint4 bq = Bf[(((kt * 4 + wn) * 2 + c2) * 32) + lane];
                #pragma unroll
                for (int m = 0; m < 2; m++) {
                    MMA16816(acc[m][c2 * 2],     A2[m], bq.x, bq.y);
                    MMA16816(acc[m][c2 * 2 + 1], A2[m], bq.z, bq.w);
                }
            }
            if (have_next)
                convert_one(q0[kt], tid + kt * NTHREADS, anext);
        }
        __syncthreads();   // A[buf^1] writes done; stage copy-out(it-1) done

        // RoPE + staged transpose (32KB stage, 64 rows)
        {
            float* stage = (float*)(smem + SMEM_ST);
            #pragma unroll
            for (int m = 0; m < 2; m++) {
                #pragma unroll
                for (int h = 0; h < 2; h++) {
                    int row = wm * 32 + m * 16 + h * 8 + gq;
                    int sw2 = row & 7;
                    float* rp = stage + row * 128 + tq;
                    #pragma unroll
                    for (int n = 0; n < 4; n++) {
                        float e = acc[m][n][h * 2];
                        float o = acc[m][n][h * 2 + 1];
                        float s = scv[n].x, c = scv[n].y;
                        int c4 = wn * 4 + n;
                        rp[((c4       ^ sw2) << 2)] = e * c - o * s;   // col d
                        rp[(((16 + c4) ^ sw2) << 2)] = e * s + o * c;  // col 64+d
                    }
                }
            }
        }
        __syncthreads();

        // coalesced copy stage -> out
        {
            const float* stage = (const float*)(smem + SMEM_ST);
            float4* od = o4 + (size_t)tile * 2048;
            #pragma unroll
            for (int i = 0; i < 8; i++) {
                int g = tid + i * NTHREADS;
                int row = g >> 5, c4 = g & 31;
                od[g] = *(const float4*)&stage[row * 128 + ((c4 ^ (row & 7)) << 2)];
            }
        }
        // no sync: next iteration's post-MMA sync orders stage reuse
    }
}

// ---------------- launcher ----------------
extern "C" void kernel_launch(void* const* d_in, const int* in_sizes, int n_in,
                              void* d_out, int out_size) {
    const float* x        = (const float*)d_in[0];
    const float* thetas   = (const float*)d_in[1];
    const float* pairs    = (const float*)d_in[2];
    const float* scale    = (const float*)d_in[3];
    const float* Rm       = (const float*)d_in[4];
    const float* inv_freq = (const float*)d_in[5];
    float*       out      = (float*)d_out;
    (void)in_sizes; (void)n_in; (void)out_size;

    cudaFuncSetAttribute(rotary_mma, cudaFuncAttributeMaxDynamicSharedMemorySize, SMEM_SZ);
    rotary_mma<<<GRID, NTHREADS, SMEM_SZ>>>(x, out, thetas, pairs, scale, Rm, inv_freq);
}

// round 16
// speedup vs baseline: 1.0690x; 1.0690x over previous
#include <cuda_runtime.h>
#include <cuda_fp16.h>
#include <cstdint>
#include <math.h>

#define SEQ   2048
#define HD    128
#define NROT  64
#define NROWS (4 * 2048 * 32)     // 262144 rows of 128
#define TILES64 (NROWS / 64)      // 4096 tiles of 64 rows
#define GRID  456                 // 3 CTAs per SM
#define NTHREADS 256

// main-kernel SMEM layout (bytes) — 64KB per CTA, 3 CTAs/SM
#define SMEM_B    0               // 32KB: B fragments fp16
#define SMEM_A    32768           // 16KB single A buf (fp16 x-tile, 64 rows)
#define SMEM_ST   49152           // 16KB f32 stage (32 rows per pass)
#define SMEM_SZ   65536

// ---------------- device globals (allocation-free scratch) ----------------
// B pack: uint4 [kt][wn][c2][lane]; uint4 = (b0,b1) for ntg=wn*4+c2*2 and ntg+1
__device__ uint4  g_Bp[8 * 4 * 2 * 32];
__device__ float2 g_SC[SEQ * 64];             // (sin, cos) per (pos, freq)

// ---------------- helpers ----------------
__device__ __forceinline__ uint32_t smem_u32(const void* p) {
    uint32_t a;
    asm("{ .reg .u64 t; cvta.to.shared.u64 t, %1; cvt.u32.u64 %0, t; }" : "=r"(a) : "l"(p));
    return a;
}

#define LDMATRIX_X4(r, addr) \
    asm volatile("ldmatrix.sync.aligned.m8n8.x4.shared.b16 {%0,%1,%2,%3}, [%4];" \
        : "=r"((r)[0]), "=r"((r)[1]), "=r"((r)[2]), "=r"((r)[3]) : "r"(addr))

#define MMA16816(d, a, b0v, b1v) \
    asm volatile("mma.sync.aligned.m16n8k16.row.col.f32.f16.f16.f32 " \
        "{%0,%1,%2,%3}, {%4,%5,%6,%7}, {%8,%9}, {%0,%1,%2,%3};" \
        : "+f"((d)[0]), "+f"((d)[1]), "+f"((d)[2]), "+f"((d)[3]) \
        : "r"((a)[0]), "r"((a)[1]), "r"((a)[2]), "r"((a)[3]), "r"(b0v), "r"(b1v))

// ---------------- prep kernel (round-14 champion) ----------------
// block 0      : build M = E1..E64 * Rm via barrier-free column-owner fold,
//                then pack all B fragments (fp16, mma frag order)
// blocks 1..128: fill the (pos, freq) sin/cos table
__global__ void prep_kernel(const float* __restrict__ thetas,
                            const float* __restrict__ pairs,
                            const float* __restrict__ scale,
                            const float* __restrict__ Rm,
                            const float* __restrict__ inv_freq) {
    const int tid = threadIdx.x;

    if (blockIdx.x > 0) {
        int base = (blockIdx.x - 1) * 1024 + tid;    // 0..131071
        #pragma unroll
        for (int r = 0; r < 4; r++) {
            int e = base + r * 256;
            int s = e >> 6, d = e & 63;
            float a = (float)s * inv_freq[d];
            float sv, cv;
            sincosf(a, &sv, &cv);
            g_SC[e] = make_float2(sv, cv);
        }
        return;
    }

    extern __shared__ float ps[];
    float (*M)[HD] = (float (*)[HD])ps;          // [128][128] = 64KB
    float* cs = ps + HD * HD;                    // cos[64]
    float* sn = cs + 64;                         // sin[64]
    int*   ij = (int*)(sn + 64);                 // i[64], j[64]

    if (tid >= 128 && tid < 192) {
        int k = tid - 128;
        float th = thetas[k] * scale[0];
        float s, c;
        sincosf(th, &s, &c);
        cs[k] = c; sn[k] = s;
        ij[k]      = (int)pairs[2 * k];
        ij[64 + k] = (int)pairs[2 * k + 1];
    }
    {
        const float4* src = (const float4*)Rm;
        float4* dst = (float4*)ps;
        #pragma unroll
        for (int i = 0; i < 16; i++) dst[tid + i * 256] = src[tid + i * 256];
    }
    __syncthreads();

    if (tid < 128) {
        const int c = tid;
        #pragma unroll 4
        for (int k = NROT - 1; k >= 0; k--) {
            int   i   = ij[k];
            int   j   = ij[64 + k];
            float cth = cs[k], sth = sn[k];
            float mi = M[i][c];
            if (i == j) {
                M[i][c] = cth * mi;
            } else {
                float mj = M[j][c];
                M[i][c] = cth * mi - sth * mj;
                M[j][c] = sth * mi + cth * mj;
            }
        }
    }
    __syncthreads();

    uint2* bp2 = (uint2*)g_Bp;
    #pragma unroll
    for (int r = 0; r < 16; r++) {
        int e = tid + r * 256;            // 0..4095
        int half = e & 1;
        int lane = (e >> 1) & 31;
        int c2   = (e >> 6) & 1;
        int wn   = (e >> 7) & 3;
        int kt   = (e >> 9) & 7;
        int tq   = lane & 3;
        int nr   = lane >> 2;
        int n    = (wn * 4 + c2 * 2 + half) * 8 + nr;
        int k0   = kt * 16 + tq * 2;
        uint32_t w[4];
        #pragma unroll
        for (int q = 0; q < 4; q++) {
            int k = k0 + (q >> 1) * 8 + (q & 1);
            __half h = __float2half_rn(M[k][n]);
            w[q] = (uint32_t)*(uint16_t*)&h;
        }
        bp2[e] = make_uint2(w[0] | (w[1] << 16), w[2] | (w[3] << 16));
    }
}

// ---------------- main kernel ----------------
// A tile SMEM layout (fp16, 16KB, 64 rows): row-major 256B/row, 16B chunks
// XOR-swizzled per 8-row group.

__device__ __forceinline__ void convert_one(float4 v, int g, uint32_t abase) {
    int r = g >> 5;
    int c = g & 31;
    __half2 p01 = __floats2half2_rn(v.x, v.y);
    __half2 p23 = __floats2half2_rn(v.z, v.w);
    uint32_t h01 = *(uint32_t*)&p01;
    uint32_t h23 = *(uint32_t*)&p23;
    uint32_t off = ((uint32_t)r << 8) + (((((uint32_t)c >> 1) ^ (r & 7)) & 15) << 4)
                 + ((c & 1) << 3);
    asm volatile("st.shared.v2.b32 [%0], {%1, %2};" :: "r"(abase + off), "r"(h01), "r"(h23));
}

__global__ void __launch_bounds__(NTHREADS, 3)
rotary_mma(const float* __restrict__ x, float* __restrict__ out) {
    extern __shared__ char smem[];
    const uint32_t sb = smem_u32(smem);
    const int tid  = threadIdx.x;
    const int bid  = blockIdx.x;
    const int warp = tid >> 5;
    const int lane = tid & 31;
    const int wm   = warp >> 2;          // 0..1 : 32-row strip (= seq-pos slot)
    const int wn   = warp & 3;           // 0..3 : 32-col strip
    const int gq   = lane >> 2;          // 0..7
    const int tq   = lane & 3;           // 0..3

    // load B fragments into SMEM (32KB)
    {
        const float4* src = (const float4*)g_Bp;
        float4* dst = (float4*)(smem + SMEM_B);
        #pragma unroll
        for (int i = 0; i < 8; i++) dst[tid + i * NTHREADS] = src[tid + i * NTHREADS];
    }

    const int nt = (TILES64 - bid + GRID - 1) / GRID;
    const float4* x4 = (const float4*)x;
    float4*       o4 = (float4*)out;
    const uint4*  Bf = (const uint4*)(smem + SMEM_B);

    // ldmatrix per-thread address pieces
    const int lr = lane & 15;
    const int lc = lane >> 4;
    const uint32_t sw = lr & 7;
    uint32_t rowoff[2];
    rowoff[0] = (uint32_t)(wm * 32 + lr) << 8;
    rowoff[1] = (uint32_t)(wm * 32 + 16 + lr) << 8;

    for (int it = 0; it < nt; it++) {
        const int tile = bid + it * GRID;

        // ---- convert phase: x tile -> fp16 in A ----
        {
            const float4* xs = x4 + (size_t)tile * 2048;
            #pragma unroll
            for (int i = 0; i < 8; i++)
                convert_one(xs[tid + i * NTHREADS], tid + i * NTHREADS, sb + SMEM_A);
        }
        __syncthreads();   // A ready (also orders B load on first iteration)

        // sin/cos for this warp's position + this thread's 4 freq columns
        float2 scv[4];
        {
            int pos = ((tile << 1) + wm) & (SEQ - 1);
            const float2* scp = g_SC + pos * 64 + wn * 16 + tq;
            #pragma unroll
            for (int n = 0; n < 4; n++) scv[n] = scp[n * 4];
        }

        // ---- MMA phase ----
        float acc[2][4][4];
        #pragma unroll
        for (int m = 0; m < 2; m++)
            #pragma unroll
            for (int n = 0; n < 4; n++)
                #pragma unroll
                for (int e = 0; e < 4; e++) acc[m][n][e] = 0.f;

        #pragma unroll
        for (int kt = 0; kt < 8; kt++) {
            uint32_t A2[2][4];
            const uint32_t choff = ((((uint32_t)(kt * 2 + lc)) ^ sw) & 15) << 4;
            #pragma unroll
            for (int m = 0; m < 2; m++)
                LDMATRIX_X4(A2[m], sb + SMEM_A + rowoff[m] + choff);
            #pragma unroll
            for (int c2 = 0; c2 < 2; c2++) {
                uint4 bq = Bf[(((kt * 4 + wn) * 2 + c2) * 32) + lane];
                #pragma unroll
                for (int m = 0; m < 2; m++) {
                    MMA16816(acc[m][c2 * 2],     A2[m], bq.x, bq.y);
                    MMA16816(acc[m][c2 * 2 + 1], A2[m], bq.z, bq.w);
                }
            }
        }
        __syncthreads();   // all A frag reads done -> A reusable next iteration

        // ---- epilogue: two passes of 32 rows through the 16KB stage ----
        float* stage = (float*)(smem + SMEM_ST);
        #pragma unroll
        for (int p = 0; p < 2; p++) {
            if (wm == p) {
                #pragma unroll
                for (int m = 0; m < 2; m++) {
                    #pragma unroll
                    for (int h = 0; h < 2; h++) {
                        int r32 = m * 16 + h * 8 + gq;        // row within pass
                        int sw2 = r32 & 7;
                        float* rp = stage + r32 * 128 + tq;
                        #pragma unroll
                        for (int n = 0; n < 4; n++) {
                            float e = acc[m][n][h * 2];
                            float o = acc[m][n][h * 2 + 1];
                            float s = scv[n].x, c = scv[n].y;
                            int c4 = wn * 4 + n;
                            rp[((c4       ^ sw2) << 2)] = e * c - o * s;  // col d
                            rp[(((16 + c4) ^ sw2) << 2)] = e * s + o * c; // col 64+d
                        }
                    }
                }
            }
            __syncthreads();
            // coalesced copy stage (32 rows) -> out
            {
                float4* od = o4 + (size_t)tile * 2048 + p * 1024;
                #pragma unroll
                for (int i = 0; i < 4; i++) {
                    int g = tid + i * NTHREADS;
                    int row = g >> 5, c4 = g & 31;
                    od[g] = *(const float4*)&stage[row * 128 + ((c4 ^ (row & 7)) << 2)];
                }
            }
            __syncthreads();
        }
    }
}

// ---------------- launcher ----------------
extern "C" void kernel_launch(void* const* d_in, const int* in_sizes, int n_in,
                              void* d_out, int out_size) {
    const float* x        = (const float*)d_in[0];
    const float* thetas   = (const float*)d_in[1];
    const float* pairs    = (const float*)d_in[2];
    const float* scale    = (const float*)d_in[3];
    const float* Rm       = (const float*)d_in[4];
    const float* inv_freq = (const float*)d_in[5];
    float*       out      = (float*)d_out;
    (void)in_sizes; (void)n_in; (void)out_size;

    const int prep_smem = (HD * HD + 64 + 64 + 128) * 4;    // 66560
    cudaFuncSetAttribute(prep_kernel, cudaFuncAttributeMaxDynamicSharedMemorySize, prep_smem);
    cudaFuncSetAttribute(rotary_mma, cudaFuncAttributeMaxDynamicSharedMemorySize, SMEM_SZ);

    prep_kernel<<<129, 256, prep_smem>>>(thetas, pairs, scale, Rm, inv_freq);
    rotary_mma<<<GRID, NTHREADS, SMEM_SZ>>>(x, out);
}

// round 17
// speedup vs baseline: 1.1078x; 1.0363x over previous
#include <cuda_runtime.h>
#include <cuda_fp16.h>
#include <cstdint>
#include <math.h>

#define SEQ   2048
#define HD    128
#define NROT  64
#define NROWS (4 * 2048 * 32)     // 262144 rows of 128
#define TILES64 (NROWS / 64)      // 4096 tiles of 64 rows
#define GRID  456                 // 3 CTAs per SM
#define NTHREADS 256

// main-kernel SMEM layout (bytes) — 48KB per CTA, 3 CTAs/SM
#define SMEM_B    0               // 32KB: B fragments fp16 (column-permuted)
#define SMEM_A    32768           // 16KB single A buf (fp16 x-tile, 64 rows)
#define SMEM_SZ   49152

// ---------------- device globals (allocation-free scratch) ----------------
// B pack: uint4 [kt][wn][c2][lane]; column-permuted so epilogue STG is contiguous
__device__ uint4  g_Bp[8 * 4 * 2 * 32];
__device__ float2 g_SC[SEQ * 64];             // (sin, cos) per (pos, freq)

// ---------------- helpers ----------------
__device__ __forceinline__ uint32_t smem_u32(const void* p) {
    uint32_t a;
    asm("{ .reg .u64 t; cvta.to.shared.u64 t, %1; cvt.u32.u64 %0, t; }" : "=r"(a) : "l"(p));
    return a;
}

#define LDMATRIX_X4(r, addr) \
    asm volatile("ldmatrix.sync.aligned.m8n8.x4.shared.b16 {%0,%1,%2,%3}, [%4];" \
        : "=r"((r)[0]), "=r"((r)[1]), "=r"((r)[2]), "=r"((r)[3]) : "r"(addr))

#define MMA16816(d, a, b0v, b1v) \
    asm volatile("mma.sync.aligned.m16n8k16.row.col.f32.f16.f16.f32 " \
        "{%0,%1,%2,%3}, {%4,%5,%6,%7}, {%8,%9}, {%0,%1,%2,%3};" \
        : "+f"((d)[0]), "+f"((d)[1]), "+f"((d)[2]), "+f"((d)[3]) \
        : "r"((a)[0]), "r"((a)[1]), "r"((a)[2]), "r"((a)[3]), "r"(b0v), "r"(b1v))

// ---------------- prep kernel ----------------
// block 0      : build M = E1..E64 * Rm via barrier-free column-owner fold,
//                then pack B fragments with the epilogue-contiguity permutation
// blocks 1..128: fill the (pos, freq) sin/cos table
__global__ void prep_kernel(const float* __restrict__ thetas,
                            const float* __restrict__ pairs,
                            const float* __restrict__ scale,
                            const float* __restrict__ Rm,
                            const float* __restrict__ inv_freq) {
    const int tid = threadIdx.x;

    if (blockIdx.x > 0) {
        int base = (blockIdx.x - 1) * 1024 + tid;    // 0..131071
        #pragma unroll
        for (int r = 0; r < 4; r++) {
            int e = base + r * 256;
            int s = e >> 6, d = e & 63;
            float a = (float)s * inv_freq[d];
            float sv, cv;
            sincosf(a, &sv, &cv);
            g_SC[e] = make_float2(sv, cv);
        }
        return;
    }

    extern __shared__ float ps[];
    float (*M)[HD] = (float (*)[HD])ps;          // [128][128] = 64KB
    float* cs = ps + HD * HD;                    // cos[64]
    float* sn = cs + 64;                         // sin[64]
    int*   ij = (int*)(sn + 64);                 // i[64], j[64]

    if (tid >= 128 && tid < 192) {
        int k = tid - 128;
        float th = thetas[k] * scale[0];
        float s, c;
        sincosf(th, &s, &c);
        cs[k] = c; sn[k] = s;
        ij[k]      = (int)pairs[2 * k];
        ij[64 + k] = (int)pairs[2 * k + 1];
    }
    {
        const float4* src = (const float4*)Rm;
        float4* dst = (float4*)ps;
        #pragma unroll
        for (int i = 0; i < 16; i++) dst[tid + i * 256] = src[tid + i * 256];
    }
    __syncthreads();

    if (tid < 128) {
        const int c = tid;
        #pragma unroll 4
        for (int k = NROT - 1; k >= 0; k--) {
            int   i   = ij[k];
            int   j   = ij[64 + k];
            float cth = cs[k], sth = sn[k];
            float mi = M[i][c];
            if (i == j) {
                M[i][c] = cth * mi;
            } else {
                float mj = M[j][c];
                M[i][c] = cth * mi - sth * mj;
                M[j][c] = sth * mi + cth * mj;
            }
        }
    }
    __syncthreads();

    // pack B fragments with the contiguity permutation:
    // y column placed at (ntg = wn*4 + nn, frag col nr) is
    //   yc = 32*wn + 8*(nr>>1) + 2*nn + (nr&1)
    uint2* bp2 = (uint2*)g_Bp;
    #pragma unroll
    for (int r = 0; r < 16; r++) {
        int e = tid + r * 256;            // 0..4095
        int half = e & 1;
        int lane = (e >> 1) & 31;
        int c2   = (e >> 6) & 1;
        int wn   = (e >> 7) & 3;
        int kt   = (e >> 9) & 7;
        int kq   = lane & 3;
        int nr   = lane >> 2;
        int nn   = c2 * 2 + half;         // n within wn group (0..3)
        int n    = wn * 32 + (nr >> 1) * 8 + nn * 2 + (nr & 1);
        int k0   = kt * 16 + kq * 2;
        uint32_t w[4];
        #pragma unroll
        for (int q = 0; q < 4; q++) {
            int k = k0 + (q >> 1) * 8 + (q & 1);
            __half h = __float2half_rn(M[k][n]);
            w[q] = (uint32_t)*(uint16_t*)&h;
        }
        bp2[e] = make_uint2(w[0] | (w[1] << 16), w[2] | (w[3] << 16));
    }
}

// ---------------- main kernel ----------------
// A tile SMEM layout (fp16, 16KB, 64 rows): row-major 256B/row, 16B chunks
// XOR-swizzled per 8-row group.

__device__ __forceinline__ void convert_one(float4 v, int g, uint32_t abase) {
    int r = g >> 5;
    int c = g & 31;
    __half2 p01 = __floats2half2_rn(v.x, v.y);
    __half2 p23 = __floats2half2_rn(v.z, v.w);
    uint32_t h01 = *(uint32_t*)&p01;
    uint32_t h23 = *(uint32_t*)&p23;
    uint32_t off = ((uint32_t)r << 8) + (((((uint32_t)c >> 1) ^ (r & 7)) & 15) << 4)
                 + ((c & 1) << 3);
    asm volatile("st.shared.v2.b32 [%0], {%1, %2};" :: "r"(abase + off), "r"(h01), "r"(h23));
}

__global__ void __launch_bounds__(NTHREADS, 3)
rotary_mma(const float* __restrict__ x, float* __restrict__ out) {
    extern __shared__ char smem[];
    const uint32_t sb = smem_u32(smem);
    const int tid  = threadIdx.x;
    const int bid  = blockIdx.x;
    const int warp = tid >> 5;
    const int lane = tid & 31;
    const int wm   = warp >> 2;          // 0..1 : 32-row strip (= seq-pos slot)
    const int wn   = warp & 3;           // 0..3 : 32-col strip
    const int gq   = lane >> 2;          // 0..7
    const int tq   = lane & 3;           // 0..3

    // load B fragments into SMEM (32KB)
    {
        const float4* src = (const float4*)g_Bp;
        float4* dst = (float4*)(smem + SMEM_B);
        #pragma unroll
        for (int i = 0; i < 8; i++) dst[tid + i * NTHREADS] = src[tid + i * NTHREADS];
    }

    const int nt = (TILES64 - bid + GRID - 1) / GRID;
    const float4* x4 = (const float4*)x;
    const uint4*  Bf = (const uint4*)(smem + SMEM_B);

    // ldmatrix per-thread address pieces
    const int lr = lane & 15;
    const int lc = lane >> 4;
    const uint32_t sw = lr & 7;
    uint32_t rowoff[2];
    rowoff[0] = (uint32_t)(wm * 32 + lr) << 8;
    rowoff[1] = (uint32_t)(wm * 32 + 16 + lr) << 8;

    for (int it = 0; it < nt; it++) {
        const int tile = bid + it * GRID;

        // ---- convert phase: x tile -> fp16 in A ----
        {
            const float4* xs = x4 + (size_t)tile * 2048;
            #pragma unroll
            for (int i = 0; i < 8; i++)
                convert_one(xs[tid + i * NTHREADS], tid + i * NTHREADS, sb + SMEM_A);
        }
        __syncthreads();   // A ready (also orders B load on first iteration)

        // sin/cos: 4 consecutive pairs at d = wn*16 + tq*4
        float2 scv[4];
        {
            int pos = ((tile << 1) + wm) & (SEQ - 1);
            const float2* scp = g_SC + pos * 64 + wn * 16 + tq * 4;
            #pragma unroll
            for (int n = 0; n < 4; n++) scv[n] = scp[n];
        }

        // ---- MMA phase ----
        float acc[2][4][4];
        #pragma unroll
        for (int m = 0; m < 2; m++)
            #pragma unroll
            for (int n = 0; n < 4; n++)
                #pragma unroll
                for (int e = 0; e < 4; e++) acc[m][n][e] = 0.f;

        #pragma unroll
        for (int kt = 0; kt < 8; kt++) {
            uint32_t A2[2][4];
            const uint32_t choff = ((((uint32_t)(kt * 2 + lc)) ^ sw) & 15) << 4;
            #pragma unroll
            for (int m = 0; m < 2; m++)
                LDMATRIX_X4(A2[m], sb + SMEM_A + rowoff[m] + choff);
            #pragma unroll
            for (int c2 = 0; c2 < 2; c2++) {
                uint4 bq = Bf[(((kt * 4 + wn) * 2 + c2) * 32) + lane];
                #pragma unroll
                for (int m = 0; m < 2; m++) {
                    MMA16816(acc[m][c2 * 2],     A2[m], bq.x, bq.y);
                    MMA16816(acc[m][c2 * 2 + 1], A2[m], bq.z, bq.w);
                }
            }
        }
        __syncthreads();   // all A frag reads done -> A reusable next iteration

        // ---- epilogue: RoPE + direct contiguous STG.128 (no SMEM, no sync) ----
        {
            float* od = out + (size_t)tile * 8192;
            #pragma unroll
            for (int m = 0; m < 2; m++) {
                #pragma unroll
                for (int h = 0; h < 2; h++) {
                    float4 lo, hi;
                    float* lop = (float*)&lo;
                    float* hip = (float*)&hi;
                    #pragma unroll
                    for (int n = 0; n < 4; n++) {
                        float e = acc[m][n][h * 2];
                        float o = acc[m][n][h * 2 + 1];
                        float s = scv[n].x, c = scv[n].y;
                        lop[n] = e * c - o * s;    // out col wn*16+tq*4+n
                        hip[n] = e * s + o * c;    // out col 64+...
                    }
                    int row = wm * 32 + m * 16 + h * 8 + gq;
                    float* rp = od + row * 128 + wn * 16 + tq * 4;
                    *(float4*)rp        = lo;
                    *(float4*)(rp + 64) = hi;
                }
            }
        }
    }
}

// ---------------- launcher ----------------
extern "C" void kernel_launch(void* const* d_in, const int* in_sizes, int n_in,
                              void* d_out, int out_size) {
    const float* x        = (const float*)d_in[0];
    const float* thetas   = (const float*)d_in[1];
    const float* pairs    = (const float*)d_in[2];
    const float* scale    = (const float*)d_in[3];
    const float* Rm       = (const float*)d_in[4];
    const float* inv_freq = (const float*)d_in[5];
    float*       out      = (float*)d_out;
    (void)in_sizes; (void)n_in; (void)out_size;

    const int prep_smem = (HD * HD + 64 + 64 + 128) * 4;    // 66560
    cudaFuncSetAttribute(prep_kernel, cudaFuncAttributeMaxDynamicSharedMemorySize, prep_smem);
    cudaFuncSetAttribute(rotary_mma, cudaFuncAttributeMaxDynamicSharedMemorySize, SMEM_SZ);

    prep_kernel<<<129, 256, prep_smem>>>(thetas, pairs, scale, Rm, inv_freq);
    rotary_mma<<<GRID, NTHREADS, SMEM_SZ>>>(x, out);
}